// round 9
// baseline (speedup 1.0000x reference)
#include <cuda_runtime.h>
#include <math.h>
#include <stdint.h>

// Problem constants
#define B_   64
#define T_   512
#define F_   513
#define H_   50
#define G_   200        // 4*H
#define M_   32768      // B*T

// Scratch (allocation-free rule: __device__ globals)
__device__ float g_xg[M_ * G_];   // 26.2 MB: x@W_ih^T + b_ih + b_hh
__device__ float g_hs[M_ * H_];   // 6.6 MB: hidden states

// ---------------------------------------------------------------------------
// tf32 split + mma + cp.async helpers
// ---------------------------------------------------------------------------
__device__ __forceinline__ void tf32_split(float x, unsigned &hi, unsigned &lo) {
    unsigned h;
    asm("cvt.rna.tf32.f32 %0, %1;" : "=r"(h) : "f"(x));
    float r = x - __uint_as_float(h);
    unsigned l;
    asm("cvt.rna.tf32.f32 %0, %1;" : "=r"(l) : "f"(r));
    hi = h; lo = l;
}

__device__ __forceinline__ void mma8(float* d, const unsigned* a,
                                     unsigned b0, unsigned b1) {
    asm volatile(
        "mma.sync.aligned.m16n8k8.row.col.f32.tf32.tf32.f32 "
        "{%0,%1,%2,%3}, {%4,%5,%6,%7}, {%8,%9}, {%0,%1,%2,%3};\n"
        : "+f"(d[0]), "+f"(d[1]), "+f"(d[2]), "+f"(d[3])
        : "r"(a[0]), "r"(a[1]), "r"(a[2]), "r"(a[3]), "r"(b0), "r"(b1));
}

// 4-byte cp.async: the 513-float row pitch (2052 B) only guarantees 4-byte
// global alignment, so 8/16-byte variants trap. src_bytes = 0 -> zero-fill.
__device__ __forceinline__ void cp_async4(uint32_t dst, const void* src, int src_bytes) {
    asm volatile("cp.async.ca.shared.global [%0], [%1], 4, %2;\n"
                 :: "r"(dst), "l"(src), "r"(src_bytes));
}
__device__ __forceinline__ void cp_commit() {
    asm volatile("cp.async.commit_group;\n");
}
template <int N>
__device__ __forceinline__ void cp_wait() {
    asm volatile("cp.async.wait_group %0;\n" :: "n"(N));
}

// ---------------------------------------------------------------------------
// Kernel A: xg = X (32768 x 513) @ W_ih^T (513 x 200) + (b_ih + b_hh)
// Block 256 threads, tile 256(M) x 40(N). Warp tile 32x40 (2 m16 tiles).
// K-chunks of 16, cp.async(4B) double-buffered. Stride 20 -> conflict-free.
// ---------------------------------------------------------------------------
#define SA 20
#define KCH 16
#define NCHUNK 33   // ceil(513/16)

__global__ __launch_bounds__(256) void xg_mma_kernel(
    const float* __restrict__ x,
    const float* __restrict__ Wih,
    const float* __restrict__ bih,
    const float* __restrict__ bhh)
{
    __shared__ float As[2][256 * SA];
    __shared__ float Bs[2][40 * SA];

    const int tid  = threadIdx.x;
    const int lane = tid & 31;
    const int w    = tid >> 5;
    const int m0   = blockIdx.x * 256;
    const int n0   = blockIdx.y * 40;
    const int g    = lane >> 2;   // 0..7
    const int c    = lane & 3;    // 0..3
    const int rw   = w * 32;

    const uint32_t sA0 = (uint32_t)__cvta_generic_to_shared(&As[0][0]);
    const uint32_t sA1 = (uint32_t)__cvta_generic_to_shared(&As[1][0]);
    const uint32_t sB0 = (uint32_t)__cvta_generic_to_shared(&Bs[0][0]);
    const uint32_t sB1 = (uint32_t)__cvta_generic_to_shared(&Bs[1][0]);

    float d[2][5][4];
#pragma unroll
    for (int m = 0; m < 2; m++)
#pragma unroll
        for (int nt = 0; nt < 5; nt++)
#pragma unroll
            for (int i = 0; i < 4; i++) d[m][nt][i] = 0.f;

    // ---- async tile issue, 4-byte ops (zero-fill past F) ----
    auto issue_chunk = [&](int kb, int buf) {
        const int kbase = kb * KCH;
        const uint32_t aB = buf ? sA1 : sA0;
        const uint32_t bB = buf ? sB1 : sB0;
        // A tile: 256 x 16 elements, 16 per thread. 16 consecutive tids
        // cover one row contiguously (64B segment) -> coalesced.
#pragma unroll
        for (int i = 0; i < 16; i++) {
            int e = tid + 256 * i;
            int r = e >> 4, k = e & 15;
            int kk = kbase + k;
            int bytes = (kk < F_) ? 4 : 0;
            const float* src = &x[(m0 + r) * F_ + ((kk < F_) ? kk : 0)];
            cp_async4(aB + (r * SA + k) * 4, src, bytes);
        }
        // B tile: 40 x 16 = 640 elements
#pragma unroll
        for (int i = 0; i < 3; i++) {
            int e = tid + 256 * i;
            if (e < 640) {
                int r = e >> 4, k = e & 15;
                int kk = kbase + k;
                int bytes = (kk < F_) ? 4 : 0;
                const float* src = &Wih[(n0 + r) * F_ + ((kk < F_) ? kk : 0)];
                cp_async4(bB + (r * SA + k) * 4, src, bytes);
            }
        }
        cp_commit();
    };

    issue_chunk(0, 0);

    int buf = 0;
    for (int kb = 0; kb < NCHUNK; kb++) {
        if (kb + 1 < NCHUNK) {
            issue_chunk(kb + 1, buf ^ 1);
            cp_wait<1>();
        } else {
            cp_wait<0>();
        }
        __syncthreads();

        const float* Ab = As[buf];
        const float* Bb = Bs[buf];
#pragma unroll
        for (int ks = 0; ks < 2; ks++) {
            const int k0 = ks * 8;
            unsigned ah[8], al[8];
#pragma unroll
            for (int m = 0; m < 2; m++) {
                float a0 = Ab[(rw + 16 * m + g)     * SA + k0 + c];
                float a1 = Ab[(rw + 16 * m + g + 8) * SA + k0 + c];
                float a2 = Ab[(rw + 16 * m + g)     * SA + k0 + c + 4];
                float a3 = Ab[(rw + 16 * m + g + 8) * SA + k0 + c + 4];
                tf32_split(a0, ah[4 * m + 0], al[4 * m + 0]);
                tf32_split(a1, ah[4 * m + 1], al[4 * m + 1]);
                tf32_split(a2, ah[4 * m + 2], al[4 * m + 2]);
                tf32_split(a3, ah[4 * m + 3], al[4 * m + 3]);
            }
#pragma unroll
            for (int nt = 0; nt < 5; nt++) {
                float b0f = Bb[(nt * 8 + g) * SA + k0 + c];
                float b1f = Bb[(nt * 8 + g) * SA + k0 + c + 4];
                unsigned bh0, bl0, bh1, bl1;
                tf32_split(b0f, bh0, bl0);
                tf32_split(b1f, bh1, bl1);
                mma8(d[0][nt], ah,     bh0, bh1);   // hi*hi
                mma8(d[0][nt], al,     bh0, bh1);   // lo*hi
                mma8(d[0][nt], ah,     bl0, bl1);   // hi*lo
                mma8(d[1][nt], ah + 4, bh0, bh1);
                mma8(d[1][nt], al + 4, bh0, bh1);
                mma8(d[1][nt], ah + 4, bl0, bl1);
            }
        }
        __syncthreads();
        buf ^= 1;
    }

    // Epilogue: + (b_ih + b_hh), float2 stores (col even, pitch 200 even)
#pragma unroll
    for (int nt = 0; nt < 5; nt++) {
        int col = n0 + nt * 8 + 2 * c;
        float bs0 = bih[col] + bhh[col];
        float bs1 = bih[col + 1] + bhh[col + 1];
#pragma unroll
        for (int m = 0; m < 2; m++) {
            int row0 = m0 + rw + 16 * m + g;
            *(float2*)&g_xg[row0 * G_ + col] =
                make_float2(d[m][nt][0] + bs0, d[m][nt][1] + bs1);
            *(float2*)&g_xg[(row0 + 8) * G_ + col] =
                make_float2(d[m][nt][2] + bs0, d[m][nt][3] + bs1);
        }
    }
}

// ---------------------------------------------------------------------------
// Kernel B: LSTM recurrence along the BATCH axis (512 chains, 64 steps).
// Thread 4j+g owns gate row g*50+j with its W_hh row in REGISTERS (no per-step
// W smem traffic). h ping-pongs in SMEM as float4 (13 broadcast LDS.128/step).
// Gates gathered to the unit's lane via shfl(width=4); c stays in a register.
// ONE barrier per step.
// ---------------------------------------------------------------------------
__device__ __forceinline__ float fast_sigmoid(float x) {
    return 1.f / (1.f + __expf(-x));
}
__device__ __forceinline__ float fast_tanh(float x) {
    float ax = fabsf(x);
    float e  = __expf(2.f * ax);          // inf for large ax -> t -> 1
    float t  = 1.f - 2.f / (1.f + e);
    return copysignf(t, x);
}

__global__ __launch_bounds__(224) void lstm_rec_kernel(
    const float* __restrict__ Whh)
{
    __shared__ float4 hbuf[2][13];   // 52 floats each (50 used, 2 zero pad)

    const int tid  = threadIdx.x;
    const int t    = blockIdx.x;
    const int j    = tid >> 2;       // hidden unit (valid < 50)
    const int g    = tid & 3;        // gate (PyTorch order i,f,g,o)
    const int row  = g * H_ + j;     // W_hh / xg gate-row index
    const bool act = (tid < 200);

    // W_hh row in registers (zero for inactive threads)
    float wv[52];
#pragma unroll
    for (int k = 0; k < 52; k++) wv[k] = 0.f;
    if (act) {
#pragma unroll
        for (int k = 0; k < H_; k++) wv[k] = __ldg(&Whh[row * H_ + k]);
    }

    // zero both h buffers (incl. pad)
    if (tid < 26) {
        ((float4*)hbuf)[tid] = make_float4(0.f, 0.f, 0.f, 0.f);
    }
    float c = 0.f;
    float pre = act ? g_xg[t * G_ + row] : 0.f;   // b=0 row index = t
    __syncthreads();

    int cur = 0;
    for (int b = 0; b < B_; b++) {
        // prefetch next step's xg (independent of h -> overlaps the dot)
        float nxt = 0.f;
        if (b + 1 < B_ && act)
            nxt = __ldg(&g_xg[((b + 1) * T_ + t) * G_ + row]);

        float a0 = pre, a1 = 0.f, a2 = 0.f, a3 = 0.f;
#pragma unroll
        for (int q = 0; q < 13; q++) {
            float4 h4 = hbuf[cur][q];
            a0 += wv[4 * q + 0] * h4.x;
            a1 += wv[4 * q + 1] * h4.y;
            a2 += wv[4 * q + 2] * h4.z;
            a3 += wv[4 * q + 3] * h4.w;
        }
        float gate = (a0 + a1) + (a2 + a3);

        // gather the 4 gates of unit j to lane g==0 (segments of width 4)
        float gf = __shfl_sync(0xffffffffu, gate, 1, 4);
        float gg = __shfl_sync(0xffffffffu, gate, 2, 4);
        float go = __shfl_sync(0xffffffffu, gate, 3, 4);

        if (g == 0 && j < H_) {
            float si = fast_sigmoid(gate);
            float sf = fast_sigmoid(gf);
            float tg = fast_tanh(gg);
            float so = fast_sigmoid(go);
            c = sf * c + si * tg;
            float hn = so * fast_tanh(c);
            ((float*)hbuf[cur ^ 1])[j] = hn;
            g_hs[(b * T_ + t) * H_ + j] = hn;
        }
        __syncthreads();
        pre = nxt;
        cur ^= 1;
    }
}

// ---------------------------------------------------------------------------
// Kernel C: out = hs (32768 x 50) @ W_out^T (50 x 513) + b_out
// tf32 mma, block 128 threads, tile 128(M) x 40(N), warp tile 32x40.
// K padded 50->56, single SMEM stage, stride 60 -> conflict-free.
// ---------------------------------------------------------------------------
#define SC 60
#define KC 56

__global__ __launch_bounds__(128) void out_mma_kernel(
    const float* __restrict__ Wout,
    const float* __restrict__ bout,
    float* __restrict__ out)
{
    __shared__ float Hs[128 * SC];
    __shared__ float Ws[40 * SC];

    const int tid  = threadIdx.x;
    const int lane = tid & 31;
    const int w    = tid >> 5;        // 0..3
    const int m0   = blockIdx.x * 128;
    const int n0   = blockIdx.y * 40;
    const int g    = lane >> 2;
    const int c    = lane & 3;
    const int rw   = w * 32;

    // hs tile 128x56 (k >= 50 zero). e over 128x64 grid, shifts only.
#pragma unroll
    for (int i = 0; i < 64; i++) {
        int e = tid + 128 * i;
        int r = e >> 6, k = e & 63;
        if (k < KC)
            Hs[r * SC + k] = (k < H_) ? g_hs[(m0 + r) * H_ + k] : 0.f;
    }
    // Wout tile 40x56 with column guard. e over 40x64.
#pragma unroll
    for (int i = 0; i < 20; i++) {
        int e = tid + 128 * i;
        int n = e >> 6, k = e & 63;
        if (n < 40 && k < KC) {
            int col = n0 + n;
            Ws[n * SC + k] = (col < F_ && k < H_) ? Wout[col * H_ + k] : 0.f;
        }
    }
    __syncthreads();

    float d[2][5][4];
#pragma unroll
    for (int m = 0; m < 2; m++)
#pragma unroll
        for (int nt = 0; nt < 5; nt++)
#pragma unroll
            for (int i = 0; i < 4; i++) d[m][nt][i] = 0.f;

#pragma unroll
    for (int ks = 0; ks < 7; ks++) {
        const int k0 = ks * 8;
        unsigned ah[8], al[8];
#pragma unroll
        for (int m = 0; m < 2; m++) {
            float a0 = Hs[(rw + 16 * m + g)     * SC + k0 + c];
            float a1 = Hs[(rw + 16 * m + g + 8) * SC + k0 + c];
            float a2 = Hs[(rw + 16 * m + g)     * SC + k0 + c + 4];
            float a3 = Hs[(rw + 16 * m + g + 8) * SC + k0 + c + 4];
            tf32_split(a0, ah[4 * m + 0], al[4 * m + 0]);
            tf32_split(a1, ah[4 * m + 1], al[4 * m + 1]);
            tf32_split(a2, ah[4 * m + 2], al[4 * m + 2]);
            tf32_split(a3, ah[4 * m + 3], al[4 * m + 3]);
        }
#pragma unroll
        for (int nt = 0; nt < 5; nt++) {
            float b0f = Ws[(nt * 8 + g) * SC + k0 + c];
            float b1f = Ws[(nt * 8 + g) * SC + k0 + c + 4];
            unsigned bh0, bl0, bh1, bl1;
            tf32_split(b0f, bh0, bl0);
            tf32_split(b1f, bh1, bl1);
            mma8(d[0][nt], ah,     bh0, bh1);
            mma8(d[0][nt], al,     bh0, bh1);
            mma8(d[0][nt], ah,     bl0, bl1);
            mma8(d[1][nt], ah + 4, bh0, bh1);
            mma8(d[1][nt], al + 4, bh0, bh1);
            mma8(d[1][nt], ah + 4, bl0, bl1);
        }
    }

    // Epilogue: + b_out, scalar stores (odd pitch 513 -> no vector align)
#pragma unroll
    for (int nt = 0; nt < 5; nt++) {
        int col = n0 + nt * 8 + 2 * c;
#pragma unroll
        for (int m = 0; m < 2; m++) {
            int row0 = m0 + rw + 16 * m + g;
            if (col < F_) {
                float bb = bout[col];
                out[row0 * F_ + col]       = d[m][nt][0] + bb;
                out[(row0 + 8) * F_ + col] = d[m][nt][2] + bb;
            }
            if (col + 1 < F_) {
                float bb = bout[col + 1];
                out[row0 * F_ + col + 1]       = d[m][nt][1] + bb;
                out[(row0 + 8) * F_ + col + 1] = d[m][nt][3] + bb;
            }
        }
    }
}

// ---------------------------------------------------------------------------
// Launch: inputs: x, W_ih, W_hh, b_ih, b_hh, W_out, b_out
// ---------------------------------------------------------------------------
extern "C" void kernel_launch(void* const* d_in, const int* in_sizes, int n_in,
                              void* d_out, int out_size)
{
    const float* x    = (const float*)d_in[0];
    const float* Wih  = (const float*)d_in[1];
    const float* Whh  = (const float*)d_in[2];
    const float* bih  = (const float*)d_in[3];
    const float* bhh  = (const float*)d_in[4];
    const float* Wout = (const float*)d_in[5];
    const float* bout = (const float*)d_in[6];
    float* out = (float*)d_out;

    dim3 gA(M_ / 256, G_ / 40);            // (128, 5)
    xg_mma_kernel<<<gA, 256>>>(x, Wih, bih, bhh);

    lstm_rec_kernel<<<T_, 224>>>(Whh);

    dim3 gC(M_ / 128, (F_ + 39) / 40);     // (256, 13)
    out_mma_kernel<<<gC, 128>>>(Wout, bout, out);
}

// round 14
// speedup vs baseline: 1.4819x; 1.4819x over previous
#include <cuda_runtime.h>
#include <math.h>
#include <stdint.h>

// Problem constants
#define B_   64
#define T_   512
#define F_   513
#define H_   50
#define G_   200        // 4*H
#define M_   32768      // B*T

// Scratch (allocation-free rule: __device__ globals)
__device__ float g_xg[M_ * G_];   // 26.2 MB: x@W_ih^T + b_ih + b_hh
__device__ float g_hs[M_ * H_];   // 6.6 MB: hidden states

// ---------------------------------------------------------------------------
// bf16 split + mma + cp.async helpers
// ---------------------------------------------------------------------------
// Split a float pair (p.x = even k, p.y = odd k) into packed bf16x2 hi and lo:
// value ~= hi + lo captures ~16 mantissa bits.
__device__ __forceinline__ void bf16_split2(float2 p, uint32_t &hi, uint32_t &lo) {
    uint32_t h;
    asm("cvt.rn.bf16x2.f32 %0, %1, %2;" : "=r"(h) : "f"(p.y), "f"(p.x));
    float h0 = __uint_as_float(h << 16);          // low  half -> even k
    float h1 = __uint_as_float(h & 0xFFFF0000u);  // high half -> odd  k
    uint32_t l;
    asm("cvt.rn.bf16x2.f32 %0, %1, %2;" : "=r"(l) : "f"(p.y - h1), "f"(p.x - h0));
    hi = h; lo = l;
}

__device__ __forceinline__ void mma16(float* d, const uint32_t* a,
                                      uint32_t b0, uint32_t b1) {
    asm volatile(
        "mma.sync.aligned.m16n8k16.row.col.f32.bf16.bf16.f32 "
        "{%0,%1,%2,%3}, {%4,%5,%6,%7}, {%8,%9}, {%0,%1,%2,%3};\n"
        : "+f"(d[0]), "+f"(d[1]), "+f"(d[2]), "+f"(d[3])
        : "r"(a[0]), "r"(a[1]), "r"(a[2]), "r"(a[3]), "r"(b0), "r"(b1));
}

// 4-byte cp.async: 513-float row pitch (2052 B) only guarantees 4-byte
// global alignment. src_bytes = 0 -> zero-fill.
__device__ __forceinline__ void cp_async4(uint32_t dst, const void* src, int src_bytes) {
    asm volatile("cp.async.ca.shared.global [%0], [%1], 4, %2;\n"
                 :: "r"(dst), "l"(src), "r"(src_bytes));
}
__device__ __forceinline__ void cp_commit() {
    asm volatile("cp.async.commit_group;\n");
}
template <int N>
__device__ __forceinline__ void cp_wait() {
    asm volatile("cp.async.wait_group %0;\n" :: "n"(N));
}

// ---------------------------------------------------------------------------
// Kernel A: xg = X (32768 x 513) @ W_ih^T (513 x 200) + (b_ih + b_hh)
// bf16 3-term mma (m16n8k16). Block 128 threads, tile 128(M) x 40(N).
// Warp tile 32x40. K-chunks of 16 (one MMA K-step), cp.async double-buffered.
// SMEM stride 24 floats (== 8 mod 16) -> conflict-free LDS.64 fragments.
// ---------------------------------------------------------------------------
#define SA 24
#define NCHUNK 33   // ceil(513/16)

__global__ __launch_bounds__(128) void xg_mma_kernel(
    const float* __restrict__ x,
    const float* __restrict__ Wih,
    const float* __restrict__ bih,
    const float* __restrict__ bhh)
{
    __shared__ float As[2][128 * SA];
    __shared__ float Bs[2][40 * SA];

    const int tid  = threadIdx.x;
    const int lane = tid & 31;
    const int w    = tid >> 5;       // 0..3
    const int m0   = blockIdx.x * 128;
    const int n0   = blockIdx.y * 40;
    const int g    = lane >> 2;      // 0..7
    const int c    = lane & 3;       // 0..3
    const int rw   = w * 32;
    const int c2   = 2 * c;

    const uint32_t sA0 = (uint32_t)__cvta_generic_to_shared(&As[0][0]);
    const uint32_t sA1 = (uint32_t)__cvta_generic_to_shared(&As[1][0]);
    const uint32_t sB0 = (uint32_t)__cvta_generic_to_shared(&Bs[0][0]);
    const uint32_t sB1 = (uint32_t)__cvta_generic_to_shared(&Bs[1][0]);

    float d[2][5][4];
#pragma unroll
    for (int m = 0; m < 2; m++)
#pragma unroll
        for (int nt = 0; nt < 5; nt++)
#pragma unroll
            for (int i = 0; i < 4; i++) d[m][nt][i] = 0.f;

    // ---- async tile issue, 4-byte ops (zero-fill past F) ----
    auto issue_chunk = [&](int kb, int buf) {
        const int kbase = kb * 16;
        const uint32_t aB = buf ? sA1 : sA0;
        const uint32_t bB = buf ? sB1 : sB0;
        // A tile: 128 x 16 elements, 16/thread; 16 consecutive tids = one row.
#pragma unroll
        for (int i = 0; i < 16; i++) {
            int e = tid + 128 * i;
            int r = e >> 4, k = e & 15;
            int kk = kbase + k;
            int bytes = (kk < F_) ? 4 : 0;
            const float* src = &x[(m0 + r) * F_ + ((kk < F_) ? kk : 0)];
            cp_async4(aB + (r * SA + k) * 4, src, bytes);
        }
        // B tile: 40 x 16 = 640 elements, 5/thread
#pragma unroll
        for (int i = 0; i < 5; i++) {
            int e = tid + 128 * i;
            int r = e >> 4, k = e & 15;
            int kk = kbase + k;
            int bytes = (kk < F_) ? 4 : 0;
            const float* src = &Wih[(n0 + r) * F_ + ((kk < F_) ? kk : 0)];
            cp_async4(bB + (r * SA + k) * 4, src, bytes);
        }
        cp_commit();
    };

    issue_chunk(0, 0);

    int buf = 0;
    for (int kb = 0; kb < NCHUNK; kb++) {
        if (kb + 1 < NCHUNK) {
            issue_chunk(kb + 1, buf ^ 1);
            cp_wait<1>();
        } else {
            cp_wait<0>();
        }
        __syncthreads();

        const float* Ab = As[buf];
        const float* Bb = Bs[buf];

        // A fragments: 2 m-tiles x 4 pairs, split once per chunk
        uint32_t ahi[8], alo[8];
#pragma unroll
        for (int m = 0; m < 2; m++) {
            int r0 = (rw + 16 * m + g) * SA;
            int r1 = (rw + 16 * m + g + 8) * SA;
            bf16_split2(*(const float2*)&Ab[r0 + c2],     ahi[4*m+0], alo[4*m+0]);
            bf16_split2(*(const float2*)&Ab[r1 + c2],     ahi[4*m+1], alo[4*m+1]);
            bf16_split2(*(const float2*)&Ab[r0 + c2 + 8], ahi[4*m+2], alo[4*m+2]);
            bf16_split2(*(const float2*)&Ab[r1 + c2 + 8], ahi[4*m+3], alo[4*m+3]);
        }
#pragma unroll
        for (int nt = 0; nt < 5; nt++) {
            int rb = (nt * 8 + g) * SA;
            uint32_t bh0, bl0, bh1, bl1;
            bf16_split2(*(const float2*)&Bb[rb + c2],     bh0, bl0);
            bf16_split2(*(const float2*)&Bb[rb + c2 + 8], bh1, bl1);
            mma16(d[0][nt], ahi,     bh0, bh1);   // hi*hi
            mma16(d[0][nt], alo,     bh0, bh1);   // lo*hi
            mma16(d[0][nt], ahi,     bl0, bl1);   // hi*lo
            mma16(d[1][nt], ahi + 4, bh0, bh1);
            mma16(d[1][nt], alo + 4, bh0, bh1);
            mma16(d[1][nt], ahi + 4, bl0, bl1);
        }
        __syncthreads();
        buf ^= 1;
    }

    // Epilogue: + (b_ih + b_hh), float2 stores (col even, pitch 200 even)
#pragma unroll
    for (int nt = 0; nt < 5; nt++) {
        int col = n0 + nt * 8 + c2;
        float bs0 = bih[col] + bhh[col];
        float bs1 = bih[col + 1] + bhh[col + 1];
#pragma unroll
        for (int m = 0; m < 2; m++) {
            int row0 = m0 + rw + 16 * m + g;
            *(float2*)&g_xg[row0 * G_ + col] =
                make_float2(d[m][nt][0] + bs0, d[m][nt][1] + bs1);
            *(float2*)&g_xg[(row0 + 8) * G_ + col] =
                make_float2(d[m][nt][2] + bs0, d[m][nt][3] + bs1);
        }
    }
}

// ---------------------------------------------------------------------------
// Kernel B: LSTM recurrence along the BATCH axis (512 chains, 64 steps).
// Thread 4j+g owns gate row g*50+j with its W_hh row in REGISTERS.
// h ping-pongs in SMEM as float4; gates gathered via shfl(width=4).
// ONE barrier per step. (unchanged from round 9)
// ---------------------------------------------------------------------------
__device__ __forceinline__ float fast_sigmoid(float x) {
    return 1.f / (1.f + __expf(-x));
}
__device__ __forceinline__ float fast_tanh(float x) {
    float ax = fabsf(x);
    float e  = __expf(2.f * ax);
    float t  = 1.f - 2.f / (1.f + e);
    return copysignf(t, x);
}

__global__ __launch_bounds__(224) void lstm_rec_kernel(
    const float* __restrict__ Whh)
{
    __shared__ float4 hbuf[2][13];   // 52 floats each (50 used, 2 zero pad)

    const int tid  = threadIdx.x;
    const int t    = blockIdx.x;
    const int j    = tid >> 2;       // hidden unit (valid < 50)
    const int g    = tid & 3;        // gate (PyTorch order i,f,g,o)
    const int row  = g * H_ + j;     // W_hh / xg gate-row index
    const bool act = (tid < 200);

    float wv[52];
#pragma unroll
    for (int k = 0; k < 52; k++) wv[k] = 0.f;
    if (act) {
#pragma unroll
        for (int k = 0; k < H_; k++) wv[k] = __ldg(&Whh[row * H_ + k]);
    }

    if (tid < 26) {
        ((float4*)hbuf)[tid] = make_float4(0.f, 0.f, 0.f, 0.f);
    }
    float c = 0.f;
    float pre = act ? g_xg[t * G_ + row] : 0.f;   // b=0 row index = t
    __syncthreads();

    int cur = 0;
    for (int b = 0; b < B_; b++) {
        float nxt = 0.f;
        if (b + 1 < B_ && act)
            nxt = __ldg(&g_xg[((b + 1) * T_ + t) * G_ + row]);

        float a0 = pre, a1 = 0.f, a2 = 0.f, a3 = 0.f;
#pragma unroll
        for (int q = 0; q < 13; q++) {
            float4 h4 = hbuf[cur][q];
            a0 += wv[4 * q + 0] * h4.x;
            a1 += wv[4 * q + 1] * h4.y;
            a2 += wv[4 * q + 2] * h4.z;
            a3 += wv[4 * q + 3] * h4.w;
        }
        float gate = (a0 + a1) + (a2 + a3);

        float gf = __shfl_sync(0xffffffffu, gate, 1, 4);
        float gg = __shfl_sync(0xffffffffu, gate, 2, 4);
        float go = __shfl_sync(0xffffffffu, gate, 3, 4);

        if (g == 0 && j < H_) {
            float si = fast_sigmoid(gate);
            float sf = fast_sigmoid(gf);
            float tg = fast_tanh(gg);
            float so = fast_sigmoid(go);
            c = sf * c + si * tg;
            float hn = so * fast_tanh(c);
            ((float*)hbuf[cur ^ 1])[j] = hn;
            g_hs[(b * T_ + t) * H_ + j] = hn;
        }
        __syncthreads();
        pre = nxt;
        cur ^= 1;
    }
}

// ---------------------------------------------------------------------------
// Kernel C: out = hs (32768 x 50) @ W_out^T (50 x 513) + b_out
// bf16 3-term mma. Block 256 threads (8 warps), tile 128(M) x 40(N),
// warp tile 16x40. K padded 50->64 (4 k16 steps), single SMEM stage,
// stride 72 (== 8 mod 16) -> conflict-free LDS.64 fragments.
// ---------------------------------------------------------------------------
#define SC 72
#define KPAD 64

__global__ __launch_bounds__(256) void out_mma_kernel(
    const float* __restrict__ Wout,
    const float* __restrict__ bout,
    float* __restrict__ out)
{
    __shared__ float Hs[128 * SC];   // 36864 B
    __shared__ float Ws[40 * SC];    // 11520 B

    const int tid  = threadIdx.x;
    const int lane = tid & 31;
    const int w    = tid >> 5;        // 0..7
    const int m0   = blockIdx.x * 128;
    const int n0   = blockIdx.y * 40;
    const int g    = lane >> 2;
    const int c    = lane & 3;
    const int rw   = w * 16;
    const int c2   = 2 * c;

    // hs tile 128x64 (k >= 50 zero), 32 iterations, coalesced within rows
#pragma unroll
    for (int i = 0; i < 32; i++) {
        int e = tid + 256 * i;
        int r = e >> 6, k = e & 63;
        Hs[r * SC + k] = (k < H_) ? g_hs[(m0 + r) * H_ + k] : 0.f;
    }
    // Wout tile 40x64 with column guard, 10 iterations
#pragma unroll
    for (int i = 0; i < 10; i++) {
        int e = tid + 256 * i;
        int n = e >> 6, k = e & 63;
        int col = n0 + n;
        Ws[n * SC + k] = (col < F_ && k < H_) ? Wout[col * H_ + k] : 0.f;
    }
    __syncthreads();

    float d[5][4];
#pragma unroll
    for (int nt = 0; nt < 5; nt++)
#pragma unroll
        for (int i = 0; i < 4; i++) d[nt][i] = 0.f;

#pragma unroll
    for (int ks = 0; ks < 4; ks++) {
        const int k0 = ks * 16;
        uint32_t ahi[4], alo[4];
        {
            int r0 = (rw + g) * SC + k0;
            int r1 = (rw + g + 8) * SC + k0;
            bf16_split2(*(const float2*)&Hs[r0 + c2],     ahi[0], alo[0]);
            bf16_split2(*(const float2*)&Hs[r1 + c2],     ahi[1], alo[1]);
            bf16_split2(*(const float2*)&Hs[r0 + c2 + 8], ahi[2], alo[2]);
            bf16_split2(*(const float2*)&Hs[r1 + c2 + 8], ahi[3], alo[3]);
        }
#pragma unroll
        for (int nt = 0; nt < 5; nt++) {
            int rb = (nt * 8 + g) * SC + k0;
            uint32_t bh0, bl0, bh1, bl1;
            bf16_split2(*(const float2*)&Ws[rb + c2],     bh0, bl0);
            bf16_split2(*(const float2*)&Ws[rb + c2 + 8], bh1, bl1);
            mma16(d[nt], ahi, bh0, bh1);
            mma16(d[nt], alo, bh0, bh1);
            mma16(d[nt], ahi, bl0, bl1);
        }
    }

    // Epilogue: + b_out, scalar stores (odd pitch 513 -> no vector align)
#pragma unroll
    for (int nt = 0; nt < 5; nt++) {
        int col = n0 + nt * 8 + c2;
        int row0 = m0 + rw + g;
        if (col < F_) {
            float bb = bout[col];
            out[row0 * F_ + col]       = d[nt][0] + bb;
            out[(row0 + 8) * F_ + col] = d[nt][2] + bb;
        }
        if (col + 1 < F_) {
            float bb = bout[col + 1];
            out[row0 * F_ + col + 1]       = d[nt][1] + bb;
            out[(row0 + 8) * F_ + col + 1] = d[nt][3] + bb;
        }
    }
}

// ---------------------------------------------------------------------------
// Launch: inputs: x, W_ih, W_hh, b_ih, b_hh, W_out, b_out
// ---------------------------------------------------------------------------
extern "C" void kernel_launch(void* const* d_in, const int* in_sizes, int n_in,
                              void* d_out, int out_size)
{
    const float* x    = (const float*)d_in[0];
    const float* Wih  = (const float*)d_in[1];
    const float* Whh  = (const float*)d_in[2];
    const float* bih  = (const float*)d_in[3];
    const float* bhh  = (const float*)d_in[4];
    const float* Wout = (const float*)d_in[5];
    const float* bout = (const float*)d_in[6];
    float* out = (float*)d_out;

    dim3 gA(M_ / 128, G_ / 40);            // (256, 5)
    xg_mma_kernel<<<gA, 128>>>(x, Wih, bih, bhh);

    lstm_rec_kernel<<<T_, 224>>>(Whh);

    dim3 gC(M_ / 128, (F_ + 39) / 40);     // (256, 13)
    out_mma_kernel<<<gC, 256>>>(Wout, bout, out);
}

// round 17
// speedup vs baseline: 1.6880x; 1.1391x over previous
#include <cuda_runtime.h>
#include <math.h>
#include <stdint.h>

// Problem constants
#define B_   64
#define T_   512
#define F_   513
#define H_   50
#define G_   200        // 4*H
#define M_   32768      // B*T

typedef unsigned long long u64;

// Scratch (allocation-free rule: __device__ globals)
__device__ float g_xg[M_ * G_];      // 26.2 MB: x@W_ih^T + b_ih + b_hh
__device__ u64   g_hsW[M_ * 25];     // 6.6 MB: h as packed bf16 (hi | lo<<32) k-pair words
__device__ u64   g_WihW[200 * 264];  // pre-split W_ih k-pair words (zero-padded past 513)
__device__ u64   g_WoutW[513 * 32];  // pre-split W_out k-pair words (zero past 50)

// ---------------------------------------------------------------------------
// Helpers
// ---------------------------------------------------------------------------
// Split a float pair (p.x = even k, p.y = odd k) into packed bf16x2 hi and lo.
__device__ __forceinline__ void bf16_split2(float2 p, uint32_t &hi, uint32_t &lo) {
    uint32_t h;
    asm("cvt.rn.bf16x2.f32 %0, %1, %2;" : "=r"(h) : "f"(p.y), "f"(p.x));
    float h0 = __uint_as_float(h << 16);
    float h1 = __uint_as_float(h & 0xFFFF0000u);
    uint32_t l;
    asm("cvt.rn.bf16x2.f32 %0, %1, %2;" : "=r"(l) : "f"(p.y - h1), "f"(p.x - h0));
    hi = h; lo = l;
}

__device__ __forceinline__ void mma16(float* d, const uint32_t* a,
                                      uint32_t b0, uint32_t b1) {
    asm volatile(
        "mma.sync.aligned.m16n8k16.row.col.f32.bf16.bf16.f32 "
        "{%0,%1,%2,%3}, {%4,%5,%6,%7}, {%8,%9}, {%0,%1,%2,%3};\n"
        : "+f"(d[0]), "+f"(d[1]), "+f"(d[2]), "+f"(d[3])
        : "r"(a[0]), "r"(a[1]), "r"(a[2]), "r"(a[3]), "r"(b0), "r"(b1));
}

__device__ __forceinline__ void cp_async4(uint32_t dst, const void* src, int src_bytes) {
    asm volatile("cp.async.ca.shared.global [%0], [%1], 4, %2;\n"
                 :: "r"(dst), "l"(src), "r"(src_bytes));
}
__device__ __forceinline__ void cp_async8(uint32_t dst, const void* src) {
    asm volatile("cp.async.ca.shared.global [%0], [%1], 8;\n"
                 :: "r"(dst), "l"(src));
}
__device__ __forceinline__ void cp_commit() {
    asm volatile("cp.async.commit_group;\n");
}
template <int N>
__device__ __forceinline__ void cp_wait() {
    asm volatile("cp.async.wait_group %0;\n" :: "n"(N));
}

// Blackwell packed f32x2 FMA (FFMA2)
__device__ __forceinline__ u64 fma2(u64 a, u64 b, u64 c) {
    u64 d;
    asm("fma.rn.f32x2 %0, %1, %2, %3;" : "=l"(d) : "l"(a), "l"(b), "l"(c));
    return d;
}
__device__ __forceinline__ float tanh_ap(float x) {
    float y;
    asm("tanh.approx.f32 %0, %1;" : "=f"(y) : "f"(x));
    return y;
}
__device__ __forceinline__ float sig_ap(float x) {
    return fmaf(0.5f, tanh_ap(0.5f * x), 0.5f);
}

// ---------------------------------------------------------------------------
// Pre-kernel: split W_ih and W_out into packed bf16 hi/lo k-pair words.
// Word w covers k = 2w, 2w+1. Deterministic; re-run every call.
// ---------------------------------------------------------------------------
#define NW_IH (200 * 264)
#define NW_OUT (513 * 32)

__global__ __launch_bounds__(256) void wsplit_kernel(
    const float* __restrict__ Wih,
    const float* __restrict__ Wout)
{
    int idx = blockIdx.x * 256 + threadIdx.x;
    if (idx < NW_IH) {
        int r = idx / 264, w = idx - r * 264;
        int k0 = 2 * w, k1 = k0 + 1;
        float f0 = (k0 < F_) ? Wih[r * F_ + k0] : 0.f;
        float f1 = (k1 < F_) ? Wih[r * F_ + k1] : 0.f;
        uint32_t hi, lo;
        bf16_split2(make_float2(f0, f1), hi, lo);
        g_WihW[idx] = (u64)hi | ((u64)lo << 32);
    } else if (idx < NW_IH + NW_OUT) {
        int e = idx - NW_IH;
        int r = e / 32, w = e - r * 32;
        int k0 = 2 * w, k1 = k0 + 1;
        float f0 = (k0 < H_) ? Wout[r * H_ + k0] : 0.f;
        float f1 = (k1 < H_) ? Wout[r * H_ + k1] : 0.f;
        uint32_t hi, lo;
        bf16_split2(make_float2(f0, f1), hi, lo);
        g_WoutW[e] = (u64)hi | ((u64)lo << 32);
    }
}

// ---------------------------------------------------------------------------
// Kernel A: xg = X (32768 x 513) @ W_ih^T (513 x 200) + (b_ih + b_hh)
// bf16 3-term mma. Block 128 threads, tile 128(M) x 40(N), warp tile 32x40.
// K-chunks of 16, cp.async double-buffered. A-tile f32 (split in loop),
// B-tile pre-split u64 words copied via cp.async8 (NO split ALU in loop).
// ---------------------------------------------------------------------------
#define SA 24
#define SBW 12          // u64 stride: conflict-free phases for LDS.64
#define NCHUNK 33       // ceil(513/16)

__global__ __launch_bounds__(128) void xg_mma_kernel(
    const float* __restrict__ x,
    const float* __restrict__ bih,
    const float* __restrict__ bhh)
{
    __shared__ float As[2][128 * SA];
    __shared__ u64   BsW[2][40 * SBW];

    const int tid  = threadIdx.x;
    const int lane = tid & 31;
    const int w    = tid >> 5;       // 0..3
    const int m0   = blockIdx.x * 128;
    const int n0   = blockIdx.y * 40;
    const int g    = lane >> 2;      // 0..7
    const int c    = lane & 3;       // 0..3
    const int rw   = w * 32;
    const int c2   = 2 * c;

    const uint32_t sA0 = (uint32_t)__cvta_generic_to_shared(&As[0][0]);
    const uint32_t sA1 = (uint32_t)__cvta_generic_to_shared(&As[1][0]);
    const uint32_t sB0 = (uint32_t)__cvta_generic_to_shared(&BsW[0][0]);
    const uint32_t sB1 = (uint32_t)__cvta_generic_to_shared(&BsW[1][0]);

    float d[2][5][4];
#pragma unroll
    for (int m = 0; m < 2; m++)
#pragma unroll
        for (int nt = 0; nt < 5; nt++)
#pragma unroll
            for (int i = 0; i < 4; i++) d[m][nt][i] = 0.f;

    auto issue_chunk = [&](int kb, int buf) {
        const int kbase = kb * 16;
        const uint32_t aB = buf ? sA1 : sA0;
        const uint32_t bB = buf ? sB1 : sB0;
        // A tile: 128 x 16 f32, 16/thread (16 consecutive tids = one row)
#pragma unroll
        for (int i = 0; i < 16; i++) {
            int e = tid + 128 * i;
            int r = e >> 4, k = e & 15;
            int kk = kbase + k;
            int bytes = (kk < F_) ? 4 : 0;
            const float* src = &x[(m0 + r) * F_ + ((kk < F_) ? kk : 0)];
            cp_async4(aB + (r * SA + k) * 4, src, bytes);
        }
        // B tile: 40 x 8 pre-split u64 words (globally zero-padded)
#pragma unroll
        for (int i = 0; i < 3; i++) {
            int e = tid + 128 * i;
            if (e < 320) {
                int r = e >> 3, wd = e & 7;
                cp_async8(bB + (r * SBW + wd) * 8,
                          &g_WihW[(n0 + r) * 264 + kb * 8 + wd]);
            }
        }
        cp_commit();
    };

    issue_chunk(0, 0);

    int buf = 0;
    for (int kb = 0; kb < NCHUNK; kb++) {
        if (kb + 1 < NCHUNK) {
            issue_chunk(kb + 1, buf ^ 1);
            cp_wait<1>();
        } else {
            cp_wait<0>();
        }
        __syncthreads();

        const float* Ab = As[buf];
        const u64*   Bb = BsW[buf];

        // A fragments: split once per chunk (owning warp only)
        uint32_t ahi[8], alo[8];
#pragma unroll
        for (int m = 0; m < 2; m++) {
            int r0 = (rw + 16 * m + g) * SA;
            int r1 = (rw + 16 * m + g + 8) * SA;
            bf16_split2(*(const float2*)&Ab[r0 + c2],     ahi[4*m+0], alo[4*m+0]);
            bf16_split2(*(const float2*)&Ab[r1 + c2],     ahi[4*m+1], alo[4*m+1]);
            bf16_split2(*(const float2*)&Ab[r0 + c2 + 8], ahi[4*m+2], alo[4*m+2]);
            bf16_split2(*(const float2*)&Ab[r1 + c2 + 8], ahi[4*m+3], alo[4*m+3]);
        }
#pragma unroll
        for (int nt = 0; nt < 5; nt++) {
            int rb = (nt * 8 + g) * SBW;
            uint2 q0 = *(const uint2*)&Bb[rb + c];       // word c:   (hi, lo)
            uint2 q1 = *(const uint2*)&Bb[rb + c + 4];   // word c+4: (hi, lo)
            mma16(d[0][nt], ahi,     q0.x, q1.x);   // hi*hi
            mma16(d[0][nt], alo,     q0.x, q1.x);   // lo*hi
            mma16(d[0][nt], ahi,     q0.y, q1.y);   // hi*lo
            mma16(d[1][nt], ahi + 4, q0.x, q1.x);
            mma16(d[1][nt], alo + 4, q0.x, q1.x);
            mma16(d[1][nt], ahi + 4, q0.y, q1.y);
        }
        __syncthreads();
        buf ^= 1;
    }

    // Epilogue: + (b_ih + b_hh), float2 stores (col even, pitch 200 even)
#pragma unroll
    for (int nt = 0; nt < 5; nt++) {
        int col = n0 + nt * 8 + c2;
        float bs0 = bih[col] + bhh[col];
        float bs1 = bih[col + 1] + bhh[col + 1];
#pragma unroll
        for (int m = 0; m < 2; m++) {
            int row0 = m0 + rw + 16 * m + g;
            *(float2*)&g_xg[row0 * G_ + col] =
                make_float2(d[m][nt][0] + bs0, d[m][nt][1] + bs1);
            *(float2*)&g_xg[(row0 + 8) * G_ + col] =
                make_float2(d[m][nt][2] + bs0, d[m][nt][3] + bs1);
        }
    }
}

// ---------------------------------------------------------------------------
// Kernel B: LSTM recurrence along the BATCH axis (512 chains, 64 steps).
// Thread 4j+g owns gate row g*50+j; W_hh row pre-paired in u64 registers,
// dot via packed f32x2 FMA (26 FFMA2 instead of 52 FFMA). h ping-pongs in
// SMEM as float4 (read as ulonglong2). Activations via tanh.approx MUFU.
// h also emitted as packed bf16 hi/lo words for kernel C. ONE barrier/step.
// ---------------------------------------------------------------------------
__global__ __launch_bounds__(224) void lstm_rec_kernel(
    const float* __restrict__ Whh)
{
    __shared__ float4 hbuf[2][13];   // 52 floats each (50 used, 2 zero pad)

    const int tid  = threadIdx.x;
    const int t    = blockIdx.x;
    const int j    = tid >> 2;       // hidden unit (valid < 50)
    const int g    = tid & 3;        // gate (PyTorch order i,f,g,o)
    const int row  = g * H_ + j;
    const bool act = (tid < 200);

    // W_hh row as 26 packed f32 pairs in registers
    u64 w2[26];
#pragma unroll
    for (int q = 0; q < 25; q++) {
        float f0 = 0.f, f1 = 0.f;
        if (act) {
            f0 = __ldg(&Whh[row * H_ + 2 * q]);
            f1 = __ldg(&Whh[row * H_ + 2 * q + 1]);
        }
        u64 p;
        asm("mov.b64 %0, {%1, %2};" : "=l"(p) : "f"(f0), "f"(f1));
        w2[q] = p;
    }
    w2[25] = 0;   // k = 50,51 pad

    if (tid < 26) {
        ((float4*)hbuf)[tid] = make_float4(0.f, 0.f, 0.f, 0.f);
    }
    float c = 0.f;
    float pre = act ? g_xg[t * G_ + row] : 0.f;   // b=0 row index = t
    __syncthreads();

    int cur = 0;
    for (int b = 0; b < B_; b++) {
        float nxt = 0.f;
        if (b + 1 < B_ && act)
            nxt = __ldg(&g_xg[((b + 1) * T_ + t) * G_ + row]);

        // dot(W_row, h) with packed f32x2 FMAs
        const ulonglong2* hb = (const ulonglong2*)&hbuf[cur][0];
        u64 acc0 = 0, acc1 = 0;
#pragma unroll
        for (int q = 0; q < 13; q++) {
            ulonglong2 h2 = hb[q];
            acc0 = fma2(w2[2 * q],     h2.x, acc0);
            acc1 = fma2(w2[2 * q + 1], h2.y, acc1);
        }
        float e0 = __uint_as_float((uint32_t)acc0);
        float o0 = __uint_as_float((uint32_t)(acc0 >> 32));
        float e1 = __uint_as_float((uint32_t)acc1);
        float o1 = __uint_as_float((uint32_t)(acc1 >> 32));
        float gate = pre + ((e0 + o0) + (e1 + o1));

        // gather the 4 gates of unit j to lane g==0 (segments of width 4)
        float gf = __shfl_sync(0xffffffffu, gate, 1, 4);
        float gg = __shfl_sync(0xffffffffu, gate, 2, 4);
        float go = __shfl_sync(0xffffffffu, gate, 3, 4);

        if (g == 0) {   // lanes 0,4,...,28 in every warp (j may exceed 49)
            float si = sig_ap(gate);
            float sf = sig_ap(gf);
            float tg = tanh_ap(gg);
            float so = sig_ap(go);
            c = fmaf(sf, c, si * tg);
            float hn = so * tanh_ap(c);
            if (j < 52) ((float*)hbuf[cur ^ 1])[j] = hn;
            // pack (h_j, h_{j+1}) as bf16 hi/lo word for kernel C
            float hnb = __shfl_down_sync(0x11111111u, hn, 4);
            if ((j & 1) == 0 && j < H_) {
                uint32_t hi, lo;
                bf16_split2(make_float2(hn, hnb), hi, lo);
                g_hsW[(b * T_ + t) * 25 + (j >> 1)] = (u64)hi | ((u64)lo << 32);
            }
        }
        __syncthreads();
        pre = nxt;
        cur ^= 1;
    }
}

// ---------------------------------------------------------------------------
// Kernel C: out = hs (32768 x 50) @ W_out^T (50 x 513) + b_out
// Both operands arrive pre-split bf16 -> mainloop is pure LDS + MMA.
// Block 256 threads, tile 128(M) x 40(N), warp tile 16x40.
// u32 stride 28 (28*dg mod 32 never in ±3 -> warp-injective, conflict-free).
// K: 3 full k16 steps (words 0..23) + 1 half step (word 24 + zero pads).
// ---------------------------------------------------------------------------
#define SH 28

__global__ __launch_bounds__(256) void out_mma_kernel(
    const float* __restrict__ bout,
    float* __restrict__ out)
{
    __shared__ uint32_t Hhi[128 * SH], Hlo[128 * SH];
    __shared__ uint32_t Whi[40 * SH],  Wlo[40 * SH];

    const int tid  = threadIdx.x;
    const int lane = tid & 31;
    const int w    = tid >> 5;        // 0..7
    const int m0   = blockIdx.x * 128;
    const int n0   = blockIdx.y * 40;
    const int g    = lane >> 2;
    const int c    = lane & 3;
    const int rw   = w * 16;
    const int c2   = 2 * c;

    // hs tile: 128 rows x 28 words (words 25..27 zero), 14/thread
#pragma unroll
    for (int i = 0; i < 14; i++) {
        int e = tid + 256 * i;
        int r = e / SH, wd = e - r * SH;
        u64 v = (wd < 25) ? g_hsW[(m0 + r) * 25 + wd] : 0ull;
        Hhi[r * SH + wd] = (uint32_t)v;
        Hlo[r * SH + wd] = (uint32_t)(v >> 32);
    }
    // W_out tile: 40 rows x 28 words, column guard
#pragma unroll
    for (int i = 0; i < 5; i++) {
        int e = tid + 256 * i;
        if (e < 40 * SH) {
            int n = e / SH, wd = e - n * SH;
            int col = n0 + n;
            u64 v = (col < F_ && wd < 25) ? g_WoutW[col * 32 + wd] : 0ull;
            Whi[n * SH + wd] = (uint32_t)v;
            Wlo[n * SH + wd] = (uint32_t)(v >> 32);
        }
    }
    __syncthreads();

    float d[5][4];
#pragma unroll
    for (int nt = 0; nt < 5; nt++)
#pragma unroll
        for (int i = 0; i < 4; i++) d[nt][i] = 0.f;

#pragma unroll
    for (int ks = 0; ks < 4; ks++) {
        const int k0w = ks * 8;
        const bool full = (ks < 3);    // ks=3: upper words (28..31) are past pad
        uint32_t ahi[4], alo[4];
        {
            int r0 = (rw + g) * SH + k0w;
            int r1 = (rw + g + 8) * SH + k0w;
            ahi[0] = Hhi[r0 + c];  alo[0] = Hlo[r0 + c];
            ahi[1] = Hhi[r1 + c];  alo[1] = Hlo[r1 + c];
            ahi[2] = full ? Hhi[r0 + c + 4] : 0u;
            alo[2] = full ? Hlo[r0 + c + 4] : 0u;
            ahi[3] = full ? Hhi[r1 + c + 4] : 0u;
            alo[3] = full ? Hlo[r1 + c + 4] : 0u;
        }
#pragma unroll
        for (int nt = 0; nt < 5; nt++) {
            int rb = (nt * 8 + g) * SH + k0w;
            uint32_t bh0 = Whi[rb + c];
            uint32_t bl0 = Wlo[rb + c];
            uint32_t bh1 = full ? Whi[rb + c + 4] : 0u;
            uint32_t bl1 = full ? Wlo[rb + c + 4] : 0u;
            mma16(d[nt], ahi, bh0, bh1);   // hi*hi
            mma16(d[nt], alo, bh0, bh1);   // lo*hi
            mma16(d[nt], ahi, bl0, bl1);   // hi*lo
        }
    }

    // Epilogue: + b_out, scalar stores (odd pitch 513 -> no vector align)
#pragma unroll
    for (int nt = 0; nt < 5; nt++) {
        int col = n0 + nt * 8 + c2;
        int row0 = m0 + rw + g;
        if (col < F_) {
            float bb = bout[col];
            out[row0 * F_ + col]       = d[nt][0] + bb;
            out[(row0 + 8) * F_ + col] = d[nt][2] + bb;
        }
        if (col + 1 < F_) {
            float bb = bout[col + 1];
            out[row0 * F_ + col + 1]       = d[nt][1] + bb;
            out[(row0 + 8) * F_ + col + 1] = d[nt][3] + bb;
        }
    }
}

// ---------------------------------------------------------------------------
// Launch: inputs: x, W_ih, W_hh, b_ih, b_hh, W_out, b_out
// ---------------------------------------------------------------------------
extern "C" void kernel_launch(void* const* d_in, const int* in_sizes, int n_in,
                              void* d_out, int out_size)
{
    const float* x    = (const float*)d_in[0];
    const float* Wih  = (const float*)d_in[1];
    const float* Whh  = (const float*)d_in[2];
    const float* bih  = (const float*)d_in[3];
    const float* bhh  = (const float*)d_in[4];
    const float* Wout = (const float*)d_in[5];
    const float* bout = (const float*)d_in[6];
    float* out = (float*)d_out;

    // Pre-split weights (deterministic, re-run every call)
    int nw = NW_IH + NW_OUT;
    wsplit_kernel<<<(nw + 255) / 256, 256>>>(Wih, Wout);

    dim3 gA(M_ / 128, G_ / 40);            // (256, 5)
    xg_mma_kernel<<<gA, 128>>>(x, bih, bhh);

    lstm_rec_kernel<<<T_, 224>>>(Whh);

    dim3 gC(M_ / 128, (F_ + 39) / 40);     // (256, 13)
    out_mma_kernel<<<gC, 256>>>(bout, out);
}